// round 17
// baseline (speedup 1.0000x reference)
#include <cuda_runtime.h>
#include <cuda_bf16.h>
#include <cstdint>

typedef unsigned int uint;

#define NB      1024
#define NIT     100000
#define NCL     10
#define DD      64
#define CH      128                  // items per chunk
#define NCH     782                  // NP / CH
#define NP      (NCH*CH)             // 100096
#define NS      37                   // item splits; grid 8x37=296 = 2/SM
#define BT      128                  // batch rows per CTA
#define NSC     98                   // sort/scatter blocks
#define GB      256                  // G1 blocks
#define HB      256                  // H blocks
#define PB      391                  // perm blocks
#define SSPAN   1024
#define LOG2E   1.4426950408889634f
#define PITCH   264

// kmain smem (relative to 1024-aligned base):
//   Ah@0 (16K) | B0@16K B1@32K | LQ0@48K LQ1 (+9216 each)
#define SM_AH   0
#define SM_B0   16384
#define SM_LQ   49152
#define LQP     72                   // logit row pitch (bytes): 64B data + 8 pad
#define LQSZ    (BT*LQP)             // 9216
#define SMEM_KM (SM_LQ + 2*LQSZ + 1024)
#define SMEM_KP (DD*PITCH*2)         // 33792 B, perm staging

// ---------------- device scratch (zero at load; kmain-fin restores) --------
__device__ float  g_G1[NCL*DD];
__device__ float  g_sums[NB*NCL];
__device__ float  g_cntf[NCL];
__device__ int    g_hist[NSC*NCL];
__device__ int    g_coff[NCL+1];
__device__ int    g_dst[NIT];
__device__ int    g_c1;              // hist-done counter
__device__ int    g_c2;              // kmain-done counter
__device__ int    g_c3;              // scatter-done counter
__device__ int    g_c4;              // G1-done counter
__device__ __align__(16) unsigned short g_Hh[NB*DD];
__device__ __align__(16) unsigned short g_W2h[(size_t)NP*DD];   // padding rows stay 0 forever

// ---------------- PTX helpers (sm_80-class baseline ISA) --------------------
__device__ __forceinline__ uint32_t smem_u32(const void* p) {
    uint32_t a;
    asm("{ .reg .u64 t; cvta.to.shared.u64 t, %1; cvt.u32.u64 %0, t; }" : "=r"(a) : "l"(p));
    return a;
}
__device__ __forceinline__ float ex2f(float x) {
    float r; asm("ex2.approx.ftz.f32 %0, %1;" : "=f"(r) : "f"(x)); return r;
}
__device__ __forceinline__ uint packbf(float lo, float hi) {
    uint r; asm("cvt.rn.bf16x2.f32 %0, %1, %2;" : "=r"(r) : "f"(hi), "f"(lo)); return r;
}
#define SW128(o) ((o) ^ (((o) >> 3) & 0x70))

__device__ __forceinline__ void cpa16(uint32_t dst, const void* src) {
    asm volatile("cp.async.cg.shared.global [%0], [%1], 16;" :: "r"(dst), "l"(src));
}
#define CPA_COMMIT() asm volatile("cp.async.commit_group;")
#define CPA_WAIT0()  asm volatile("cp.async.wait_group 0;" ::: "memory")

#define LDSM4(R, A) \
    asm volatile("ldmatrix.sync.aligned.m8n8.x4.shared.b16 {%0,%1,%2,%3}, [%4];" \
        : "=r"((R)[0]), "=r"((R)[1]), "=r"((R)[2]), "=r"((R)[3]) : "r"(A))

#define STS32(A, V) \
    asm volatile("st.shared.u32 [%0], %1;" :: "r"(A), "r"(V) : "memory")
#define LDS64(R0, R1, A) \
    asm volatile("ld.shared.v2.u32 {%0,%1}, [%2];" : "=r"(R0), "=r"(R1) : "r"(A))

__device__ __forceinline__ void mma_bf16(float* c, const uint* a, uint b0, uint b1) {
    asm volatile("mma.sync.aligned.m16n8k16.row.col.f32.bf16.bf16.f32 "
        "{%0,%1,%2,%3}, {%4,%5,%6,%7}, {%8,%9}, {%0,%1,%2,%3};"
        : "+f"(c[0]), "+f"(c[1]), "+f"(c[2]), "+f"(c[3])
        : "r"(a[0]), "r"(a[1]), "r"(a[2]), "r"(a[3]), "r"(b0), "r"(b1));
}

// ===========================================================================
// Kernel 1: kprep — unchanged from R16 (hist/scan/scatter + G1 + H + perm)
// ===========================================================================
__global__ void __launch_bounds__(320) kprep(const int* __restrict__ cl,
                                             const float* __restrict__ W1,
                                             const float* __restrict__ W2,
                                             const float* __restrict__ inp) {
    int t = threadIdx.x, lane = t & 31, w = t >> 5;
    int bid = blockIdx.x;

    if (bid >= NSC + GB + HB) {
        // ================= perm phase =================
        if (t >= 256) return;
        __shared__ int ok;
        if (t == 0) {
            while (*(volatile int*)&g_c3 != NSC) __nanosleep(128);
            ok = 1;
        }
        __syncthreads();
        (void)ok;
        __threadfence();
        extern __shared__ unsigned short shh[];
        int pid = bid - (NSC + GB + HB);
        int i = pid * 256 + t;
#pragma unroll 8
        for (int d = 0; d < DD; d++) {
            float x = (i < NIT) ? W2[(size_t)d*NIT + i] : 0.0f;
            shh[d*PITCH + t] = __bfloat16_as_ushort(__float2bfloat16(x));
        }
        __syncthreads();
        if (i >= NIT) return;
        int dp = g_dst[i];
        uint v[32];
#pragma unroll
        for (int j = 0; j < 32; j++)
            v[j] = (uint)shh[(2*j)*PITCH + t] | ((uint)shh[(2*j+1)*PITCH + t] << 16);
        uint4* dh = (uint4*)(g_W2h + (size_t)dp*DD);
#pragma unroll
        for (int q = 0; q < 8; q++) dh[q] = make_uint4(v[4*q], v[4*q+1], v[4*q+2], v[4*q+3]);
        return;
    }

    if (bid >= NSC + GB) {
        // ================= H phase: wait for G1 =================
        if (t >= 256) return;
        __shared__ int ok;
        if (t == 0) {
            while (*(volatile int*)&g_c4 != GB) __nanosleep(128);
            ok = 1;
        }
        __syncthreads();
        (void)ok;
        __threadfence();
        int e = (bid - (NSC + GB)) * 256 + t;   // 0..65535
        int b = e >> 6, d = e & 63;
        float a = 0.0f;
#pragma unroll
        for (int c = 0; c < NCL; c++) a += inp[b*NCL + c] * g_G1[c*DD + d];
        g_Hh[b*DD + d] = __bfloat16_as_ushort(__float2bfloat16(a * LOG2E));
        return;
    }

    if (bid >= NSC) {
        // ================= G1 phase: 16 items in flight ========
        if (t >= 256) return;
        int d = t & 63;
        int stripe = (bid - NSC)*4 + (t >> 6);
        const int ns = GB*4;
        float acc[NCL];
#pragma unroll
        for (int k = 0; k < NCL; k++) acc[k] = 0.0f;
        int i = stripe;
        for (; i + 15*ns < NIT; i += 16*ns) {
            int cc[16]; float wv[16];
#pragma unroll
            for (int j = 0; j < 16; j++) cc[j] = cl[i + j*ns];
#pragma unroll
            for (int j = 0; j < 16; j++) wv[j] = W1[(size_t)(i + j*ns)*DD + d];
#pragma unroll
            for (int k = 0; k < NCL; k++) {
#pragma unroll
                for (int j = 0; j < 16; j++) if (cc[j] == k) acc[k] += wv[j];
            }
        }
        for (; i < NIT; i += ns) {
            int c = cl[i];
            float w0 = W1[(size_t)i*DD + d];
#pragma unroll
            for (int k = 0; k < NCL; k++) if (c == k) acc[k] += w0;
        }
#pragma unroll
        for (int k = 0; k < NCL; k++) atomicAdd(&g_G1[k*DD + d], acc[k]);
        __syncthreads();
        if (t == 0) { __threadfence(); atomicAdd(&g_c4, 1); }
        return;
    }

    // ================= hist -> scan -> scatter =================
    __shared__ int h[NCL];
    if (t < NCL) h[t] = 0;
    __syncthreads();
    int base = bid * SSPAN;
    if (t < 256) {
        int cnt[NCL];
#pragma unroll
        for (int k = 0; k < NCL; k++) cnt[k] = 0;
#pragma unroll
        for (int q = 0; q < 4; q++) {
            int i = base + q*256 + t;
            if (i < NIT) {
                int c = cl[i];
#pragma unroll
                for (int k = 0; k < NCL; k++) if (c == k) cnt[k]++;
            }
        }
#pragma unroll
        for (int k = 0; k < NCL; k++) if (cnt[k]) atomicAdd(&h[k], cnt[k]);
    }
    __syncthreads();
    if (t < NCL) g_hist[bid*NCL + t] = h[t];
    __threadfence();
    __syncthreads();
    if (t == 0) {
        atomicAdd(&g_c1, 1);
        while (*(volatile int*)&g_c1 != NSC) __nanosleep(64);
    }
    __syncthreads();

    __shared__ int run[NCL];
    __shared__ int wc[8][NCL];
    __shared__ int tot_s[NCL], pre_s[NCL];
    if (w < NCL) {
        int c = w, full = 0, pre = 0;
        for (int b = lane; b < NSC; b += 32) {
            int v = g_hist[b*NCL + c];
            full += v;
            if (b < bid) pre += v;
        }
#pragma unroll
        for (int o = 16; o; o >>= 1) {
            full += __shfl_xor_sync(~0u, full, o);
            pre  += __shfl_xor_sync(~0u, pre,  o);
        }
        if (!lane) { tot_s[c] = full; pre_s[c] = pre; }
    }
    __syncthreads();
    if (t == 0) {
        int r = 0;
        for (int k = 0; k < NCL; k++) {
            int o = r; r += tot_s[k];
            run[k] = o + pre_s[k];
            if (bid == 0) { g_coff[k] = o; g_cntf[k] = (float)tot_s[k]; }
        }
        if (bid == 0) g_coff[NCL] = r;
    }
    __syncthreads();

    unsigned ltm = (1u << lane) - 1u;
    for (int q = 0; q < 4; q++) {
        if (t < 80) ((int*)wc)[t] = 0;
        __syncthreads();
        int i = base + q*256 + t;
        int c = (t < 256 && i < NIT) ? cl[i] : -1;
        unsigned mm = __match_any_sync(0xffffffffu, c);
        int myrank = __popc(mm & ltm);
        if (c >= 0 && myrank == 0) wc[w][c] = __popc(mm);
        __syncthreads();
        if (t < NCL) {
            int k = t, s = run[k];
            for (int ww = 0; ww < 8; ww++) { int tmp = wc[ww][k]; wc[ww][k] = s; s += tmp; }
            run[k] = s;
        }
        __syncthreads();
        if (c >= 0) g_dst[i] = wc[w][c] + myrank;
        __syncthreads();
    }
    __threadfence();
    __syncthreads();
    if (t == 0) atomicAdd(&g_c3, 1);
}

// ===========================================================================
// Kernel 2: kmain — warp-specialized: warps 0-3 MMA producers, 4-7 exp
// consumers. Logits staged as bf16x2 in double-buffered smem quarters.
// ===========================================================================

// producer: MMA one 32-item quarter for rows [wb, wb+32), store bf16 logits
__device__ __forceinline__ void produce(uint32_t bq, int q, const uint (*ah)[4],
                                        const int* bx, uint32_t lq, int wb, int lane) {
    float acc[2][4][4];
#pragma unroll
    for (int a = 0; a < 2; a++)
#pragma unroll
        for (int b = 0; b < 4; b++)
#pragma unroll
            for (int c = 0; c < 4; c++) acc[a][b][c] = 0.0f;
#pragma unroll
    for (int ks = 0; ks < 4; ks++) {
        uint r0[4], r1[4];
        LDSM4(r0, bq + (2*q)*2048 + bx[ks]);
        LDSM4(r1, bq + (2*q+1)*2048 + bx[ks]);
#pragma unroll
        for (int mt = 0; mt < 2; mt++) {
            mma_bf16(acc[mt][0], ah[mt*4 + ks], r0[0], r0[1]);
            mma_bf16(acc[mt][1], ah[mt*4 + ks], r0[2], r0[3]);
            mma_bf16(acc[mt][2], ah[mt*4 + ks], r1[0], r1[1]);
            mma_bf16(acc[mt][3], ah[mt*4 + ks], r1[2], r1[3]);
        }
    }
    int rb = wb + (lane >> 2);
    int cb = (lane & 3) * 4;      // byte offset of col pair within n-tile
#pragma unroll
    for (int mt = 0; mt < 2; mt++) {
        int rr0 = rb + mt*16;
#pragma unroll
        for (int nt = 0; nt < 4; nt++) {
            uint lo = packbf(acc[mt][nt][0], acc[mt][nt][1]);   // row rr0
            uint hi = packbf(acc[mt][nt][2], acc[mt][nt][3]);   // row rr0+8
            STS32(lq + (uint)(rr0*LQP + nt*16 + cb), lo);
            STS32(lq + (uint)((rr0 + 8)*LQP + nt*16 + cb), hi);
        }
    }
}

// consumer: ex2 + segment-accumulate one 32-item quarter for one row
__device__ __forceinline__ void consume(uint32_t lq, int row, bool fast, int qpos,
                                        int bpos, float& s0, float& s1) {
    uint v[16];
    uint32_t a = lq + (uint)(row*LQP);
#pragma unroll
    for (int k = 0; k < 8; k++) LDS64(v[2*k], v[2*k+1], a + k*8);
    if (fast) {
        float s = 0.0f;
#pragma unroll
        for (int k = 0; k < 16; k++) {
            s += ex2f(__uint_as_float(v[k] << 16));
            s += ex2f(__uint_as_float(v[k] & 0xffff0000u));
        }
        s0 += s;
    } else {
#pragma unroll
        for (int k = 0; k < 16; k++) {
            float e0 = ex2f(__uint_as_float(v[k] << 16));
            float e1 = ex2f(__uint_as_float(v[k] & 0xffff0000u));
            int p = qpos + 2*k;
            if (p < bpos)          s0 += e0;
            else if (p < NIT)      s1 += e0;
            if (p + 1 < bpos)      s0 += e1;
            else if (p + 1 < NIT)  s1 += e1;
        }
    }
}

// B staging by the 128 consumer threads
__device__ __forceinline__ void stage_B128(uint32_t sb, int buf, int ch, int ct) {
    uint32_t bh = sb + SM_B0 + buf*16384;
    const char* gh = (const char*)g_W2h + (size_t)ch*CH*128;
#pragma unroll
    for (int qq = 0; qq < 8; qq++) {
        int off = (ct + qq*128) * 16;
        cpa16(bh + SW128(off), gh + off);
    }
}

__global__ void __launch_bounds__(256, 2) kmain(float* __restrict__ out) {
    extern __shared__ char dsm[];
    __shared__ int coff_s[NCL+1];
    __shared__ int slast;
    uint32_t sb0 = smem_u32(dsm);
    uint32_t pad = (1024u - (sb0 & 1023u)) & 1023u;
    uint32_t sb  = sb0 + pad;

    int t = threadIdx.x, lane = t & 31, w = t >> 5;
    int bbase = blockIdx.x * BT;
    int ch_lo = (blockIdx.y * NCH) / NS;          // balanced 21-22 chunk ranges
    int ch_hi = ((blockIdx.y + 1) * NCH) / NS;
    int n = ch_hi - ch_lo;

    if (t < NCL+1) coff_s[t] = g_coff[t];

    // ---- prologue: stage A (Hh) and B chunk 0 with all 256 threads ----
    {
        const char* gh = (const char*)g_Hh + (size_t)bbase*128;
        const char* gb = (const char*)g_W2h + (size_t)ch_lo*CH*128;
#pragma unroll
        for (int qq = 0; qq < 4; qq++) {
            int off = (t + qq*256) * 16;
            cpa16(sb + SM_AH + SW128(off), gh + off);
            cpa16(sb + SM_B0 + SW128(off), gb + off);
        }
    }
    CPA_COMMIT();
    CPA_WAIT0();
    __syncthreads();

    // producer-only state
    uint ah[8][4];
    int bx[4];
    int wb = (w & 3) * 32;
    if (w < 4) {
        int m  = lane >> 3, rl = lane & 7;
        int rowb = ((m >> 1) << 3) + rl;
        int kadd = m & 1;
#pragma unroll
        for (int ks = 0; ks < 4; ks++)
            bx[ks] = rowb*128 + ((ks*32 + kadd*16) ^ (rl*16));
#pragma unroll
        for (int mt = 0; mt < 2; mt++) {
            int arow = wb + mt*16 + ((lane >> 3) & 1)*8 + rl;
#pragma unroll
            for (int ks = 0; ks < 4; ks++) {
                int au = ks*2 + (lane >> 4);
                LDSM4(ah[mt*4 + ks], sb + SM_AH + arow*128 + ((au*16) ^ (rl*16)));
            }
        }
    }

    // consumer-only state
    int row  = t & 127;                 // consumer: one thread per batch row
    int grow = bbase + row;
    float s0 = 0.f, s1 = 0.f;
    int cur = 0;
    { int ib = ch_lo * CH; while (coff_s[cur+1] <= ib) cur++; }
    int bpos = 0, qibase = 0;
    bool fast = false;

    // ---- quarter-pipelined producer/consumer loop ----
    int totalq = 4 * n;
    for (int j = 0; j <= totalq; j++) {
        if (w < 4) {
            if (j < totalq) {
                int ch = j >> 2, q = j & 3;
                uint32_t bq = sb + SM_B0 + (ch & 1)*16384;
                uint32_t lq = sb + SM_LQ + (j & 1)*LQSZ;
                produce(bq, q, (const uint(*)[4])ah, bx, lq, wb, lane);
            }
        } else if (j >= 1) {
            int cq = j - 1;
            int ch = cq >> 2, q = cq & 3;
            if (q == 0) {
                qibase = (ch_lo + ch) * CH;
                int nc = cur;
                while (coff_s[nc+1] <= qibase) nc++;
                if (nc != cur) {
                    atomicAdd(&g_sums[grow*NCL + cur], s0);
                    if (cur + 1 < NCL) atomicAdd(&g_sums[grow*NCL + cur + 1], s1);
                    s0 = 0.f; s1 = 0.f; cur = nc;
                }
                bpos = coff_s[cur+1];
                fast = (qibase + CH <= bpos);
                if (ch + 1 < n) { stage_B128(sb, (ch+1) & 1, ch_lo + ch + 1, row); CPA_COMMIT(); }
            }
            consume(sb + SM_LQ + (cq & 1)*LQSZ, row, fast, qibase + q*32, bpos, s0, s1);
            if (q == 3 && ch + 1 < n) CPA_WAIT0();
        }
        __syncthreads();
    }

    if (w >= 4) {
        atomicAdd(&g_sums[grow*NCL + cur], s0);
        if (cur + 1 < NCL) atomicAdd(&g_sums[grow*NCL + cur + 1], s1);
    }

    // ---- fused finalize: last CTA computes output + restores scratch -----
    __threadfence();
    __syncthreads();
    if (t == 0) slast = (atomicAdd(&g_c2, 1) == (int)(gridDim.x*gridDim.y) - 1);
    __syncthreads();
    if (slast) {
        __threadfence();
        for (int b = t; b < NB; b += 256) {
            float v[NCL], z = 0.0f;
#pragma unroll
            for (int c = 0; c < NCL; c++) { v[c] = g_sums[b*NCL + c]; z += v[c]; }
            float invz = 1.0f / z;
#pragma unroll
            for (int c = 0; c < NCL; c++)
                out[b*NCL + c] = v[c] * invz / fmaxf(g_cntf[c], 1.0f);
#pragma unroll
            for (int c = 0; c < NCL; c++) g_sums[b*NCL + c] = 0.0f;
        }
        for (int i = t; i < NCL*DD; i += 256) g_G1[i] = 0.0f;
        if (t == 0) { g_c1 = 0; g_c2 = 0; g_c3 = 0; g_c4 = 0; }
    }
}

// ---------------------------------------------------------------------------
extern "C" void kernel_launch(void* const* d_in, const int* in_sizes, int n_in,
                              void* d_out, int out_size) {
    const float* input = (const float*)d_in[0];   // (1024, 10) f32
    const int*   clust = (const int*)d_in[1];     // (100000,) i32
    const float* W1    = (const float*)d_in[2];   // (100000, 64) f32
    const float* W2    = (const float*)d_in[3];   // (64, 100000) f32
    float*       out   = (float*)d_out;           // (1024, 10) f32

    cudaFuncSetAttribute(kmain, cudaFuncAttributeMaxDynamicSharedMemorySize, SMEM_KM);
    cudaFuncSetAttribute(kprep, cudaFuncAttributeMaxDynamicSharedMemorySize, SMEM_KP);

    kprep<<<NSC + GB + HB + PB, 320, SMEM_KP>>>(clust, W1, W2, input);
    dim3 grid(NB / BT, NS);
    kmain<<<grid, 256, SMEM_KM>>>(out);
}